// round 10
// baseline (speedup 1.0000x reference)
#include <cuda_runtime.h>

#define BB 2
#define SS 2048
#define DD 128
#define HH 8
#define EPSF 1e-10f
#define FULLM 0xffffffffu
#define TTBLK 64                 // phase-1 blocks (4096 rows, 8 thr/row, 512 thr/blk)
#define NROWS (BB * HH * SS)     // 32768 output rows
#define QROW  (SS / 4)           // 512 float4 per row

// Scratch (allocation-free rule: __device__ globals; zero-init at load)
__device__ int      g_tt[BB * SS];
__device__ int      g_ng[BB * SS];   // next_global per (b,s)
__device__ unsigned g_cnt  = 0;
__device__ unsigned g_flag = 0;

__device__ __forceinline__ unsigned ld_acquire_u32(const unsigned* p) {
    unsigned v;
    asm volatile("ld.acquire.gpu.global.u32 %0, [%1];" : "=r"(v) : "l"(p) : "memory");
    return v;
}

// Per-lane partial for row `row`, sub-lane r in [0,8): EXACT summation order
// shared by phase-1 and row-writer so tt is bitwise identical in both.
__device__ __forceinline__ void row_partials(const float* __restrict__ x,
                                             const float* __restrict__ W,
                                             int row, int r,
                                             float& a0, float& a1, float& a2) {
    const float4* xr = reinterpret_cast<const float4*>(x + (size_t)row * DD);
    const float4* W4 = reinterpret_cast<const float4*>(W);
    float4 xv[4];
    #pragma unroll
    for (int i = 0; i < 4; i++) xv[i] = xr[r * 4 + i];
    a0 = 0.f; a1 = 0.f; a2 = 0.f;
    #pragma unroll
    for (int i = 0; i < 4; i++) {
        int cc = r * 4 + i;
        float4 w0 = W4[cc];
        float4 w1 = W4[32 + cc];
        float4 w2 = W4[64 + cc];
        a0 += xv[i].x * w0.x + xv[i].y * w0.y + xv[i].z * w0.z + xv[i].w * w0.w;
        a1 += xv[i].x * w1.x + xv[i].y * w1.y + xv[i].z * w1.z + xv[i].w * w1.w;
        a2 += xv[i].x * w2.x + xv[i].y * w2.y + xv[i].z * w2.z + xv[i].w * w2.w;
    }
    #pragma unroll
    for (int off = 4; off; off >>= 1) {       // 8-lane butterfly (xor groups)
        a0 += __shfl_xor_sync(FULLM, a0, off);
        a1 += __shfl_xor_sync(FULLM, a1, off);
        a2 += __shfl_xor_sync(FULLM, a2, off);
    }
}

__device__ __forceinline__ int pick_tt(float a0, float a1, float a2,
                                       const float* __restrict__ gu,
                                       const float* __restrict__ bias, int row) {
    const float* gr = gu + (size_t)row * 3;
    float g0 = -logf(-logf(gr[0] + EPSF) + EPSF);
    float g1 = -logf(-logf(gr[1] + EPSF) + EPSF);
    float g2 = -logf(-logf(gr[2] + EPSF) + EPSF);
    float s0 = a0 + bias[0] + g0;
    float s1 = a1 + bias[1] + g1;
    float s2 = a2 + bias[2] + g2;
    int tt = 0; float best = s0;
    if (s1 > best) { best = s1; tt = 1; }     // first-max tie-break
    if (s2 > best) { best = s2; tt = 2; }
    return tt;
}

__global__ void __launch_bounds__(512) k_fused(const float* __restrict__ x,
                                               const float* __restrict__ gu,
                                               const float* __restrict__ W,
                                               const float* __restrict__ bias,
                                               float4* __restrict__ out) {
    const int tid = threadIdx.x;
    const int bid = blockIdx.x;

    // ======================= Phase-1: blocks 0..63 =======================
    if (bid < TTBLK) {
        __shared__ int sh_last;
        __shared__ int sh_wmin[16];
        __shared__ int sh_wsuf[16];
        {
            int gid = bid * 512 + tid;
            int row = gid >> 3;              // 0..4095
            int r   = gid & 7;
            float a0, a1, a2;
            row_partials(x, W, row, r, a0, a1, a2);
            if (r == 0) g_tt[row] = pick_tt(a0, a1, a2, gu, bias, row);
        }
        __syncthreads();
        if (tid == 0) {
            __threadfence();                              // release g_tt
            sh_last = (atomicAdd(&g_cnt, 1u) == TTBLK - 1);
        }
        __syncthreads();
        if (!sh_last) return;

        // ---- last block: suffix-min scan per batch, publish g_ng + flag ----
        __threadfence();                                  // acquire all g_tt
        int lane = tid & 31, wid = tid >> 5;              // 16 warps
        for (int b = 0; b < BB; b++) {
            __syncthreads();
            int base = b * SS + tid * 4;
            int t0 = g_tt[base + 0], t1 = g_tt[base + 1];
            int t2 = g_tt[base + 2], t3 = g_tt[base + 3];
            int j0 = tid * 4;
            int e0 = (t0 == 0) ? j0     : SS;
            int e1 = (t1 == 0) ? j0 + 1 : SS;
            int e2 = (t2 == 0) ? j0 + 2 : SS;
            int e3 = (t3 == 0) ? j0 + 3 : SS;
            int m  = min(min(e0, e1), min(e2, e3));

            int inc = m;                                  // warp suffix-min
            #pragma unroll
            for (int off = 1; off < 32; off <<= 1) {
                int v = __shfl_down_sync(FULLM, inc, off);
                if (lane + off < 32) inc = min(inc, v);
            }
            int excl = __shfl_down_sync(FULLM, inc, 1);
            if (lane == 31) excl = SS;

            if (lane == 0) sh_wmin[wid] = inc;
            __syncthreads();
            if (wid == 0) {
                int wm = (lane < 16) ? sh_wmin[lane] : SS;
                int winc = wm;
                #pragma unroll
                for (int off = 1; off < 16; off <<= 1)
                    winc = min(winc, __shfl_down_sync(FULLM, winc, off));
                int wex = __shfl_down_sync(FULLM, winc, 1);  // lane15 <- SS
                if (lane < 16) sh_wsuf[lane] = wex;
            }
            __syncthreads();
            int after = min(excl, sh_wsuf[wid]);          // min over idx > 4t+3

            int run = after;
            int ng3 = run; run = min(run, e3);
            int ng2 = run; run = min(run, e2);
            int ng1 = run; run = min(run, e1);
            int ng0 = run;
            g_ng[base + 0] = ng0; g_ng[base + 1] = ng1;
            g_ng[base + 2] = ng2; g_ng[base + 3] = ng3;
        }
        __syncthreads();
        if (tid == 0) {
            __threadfence();           // release g_ng
            g_cnt = 0;                 // reset for next graph replay
            atomicExch(&g_flag, 1u);   // idempotent across replays
        }
        return;
    }

    // ======================= Row writers: one full row each =================
    int rb = bid - TTBLK;              // 0..32767
    int s  = rb & (SS - 1);
    int b  = rb >> 14;                 // / (H*S)
    int xrow = b * SS + s;

    __shared__ int sh_tt;
    __shared__ int sh_ng;
    if (tid < 32) {                    // warp 0 recomputes tt (bitwise == phase-1)
        int r = tid & 7;               // 4 identical 8-lane groups (keeps idx in range)
        float a0, a1, a2;
        row_partials(x, W, xrow, r, a0, a1, a2);
        if (tid == 0) sh_tt = pick_tt(a0, a1, a2, gu, bias, xrow);
    }
    __syncthreads();
    int tt = sh_tt;

    int lo = 0, hi = s;
    if (tt == 1) { lo = s; hi = s; }
    else if (tt == 2) {
        if (tid == 0) {                // only ~1/3 of blocks reach this spin
            while (ld_acquire_u32(&g_flag) == 0) __nanosleep(64);
            sh_ng = g_ng[xrow];
        }
        __syncthreads();
        hi = min(s, sh_ng);
    }

    // Full aligned 8KB row: 512 threads x one float4, branchless in-range test.
    int j = tid << 2;
    unsigned range = (unsigned)(hi - lo);
    float4 v;
    v.x = ((unsigned)(j     - lo) <= range) ? 1.f : 0.f;
    v.y = ((unsigned)(j + 1 - lo) <= range) ? 1.f : 0.f;
    v.z = ((unsigned)(j + 2 - lo) <= range) ? 1.f : 0.f;
    v.w = ((unsigned)(j + 3 - lo) <= range) ? 1.f : 0.f;
    __stcs(&out[(size_t)rb * QROW + tid], v);
}

extern "C" void kernel_launch(void* const* d_in, const int* in_sizes, int n_in,
                              void* d_out, int out_size) {
    const float* x    = (const float*)d_in[0];  // input_tensor (B,S,D)
    // d_in[1] = token_types (unused by reference)
    const float* gu   = (const float*)d_in[2];  // gumbel_u (B,S,3)
    const float* W    = (const float*)d_in[3];  // (3,D)
    const float* bias = (const float*)d_in[4];  // (3,)
    float4* out = (float4*)d_out;

    k_fused<<<TTBLK + NROWS, 512>>>(x, gu, W, bias, out);
}

// round 11
// speedup vs baseline: 2.4844x; 2.4844x over previous
#include <cuda_runtime.h>

#define BB 2
#define SS 2048
#define DD 128
#define HH 8
#define EPSF 1e-10f
#define FULLM 0xffffffffu
#define TTBLK 64                 // phase-1 blocks (4096 rows, 8 thr/row, 512 thr/blk)
#define NROWS (BB * HH * SS)     // 32768 output rows
#define QROW  (SS / 4)           // 512 float4 per row

// Scratch (allocation-free rule: __device__ globals; zero-init at load)
__device__ int      g_tt[BB * SS];
__device__ int2     g_lohi[BB * SS];
__device__ unsigned g_cnt = 0;

// ---------------------------------------------------------------------------
// Kernel 1 (grid 64): tt argmax + suffix-min scan -> g_lohi.
// Exact logic validated in R7/R8 (rel_err = 0).
// ---------------------------------------------------------------------------
__global__ void __launch_bounds__(512) k_phase1(const float* __restrict__ x,
                                                const float* __restrict__ gu,
                                                const float* __restrict__ W,
                                                const float* __restrict__ bias) {
    const int tid = threadIdx.x;
    const int bid = blockIdx.x;

    __shared__ int sh_last;
    __shared__ int sh_wmin[16];
    __shared__ int sh_wsuf[16];

    {
        int gid = bid * 512 + tid;
        int row = gid >> 3;              // 0..4095 = b*S + s
        int r   = gid & 7;

        const float4* xr = reinterpret_cast<const float4*>(x + (size_t)row * DD);
        const float4* W4 = reinterpret_cast<const float4*>(W);

        float4 xv[4];
        #pragma unroll
        for (int i = 0; i < 4; i++) xv[i] = xr[r * 4 + i];

        float a0 = 0.f, a1 = 0.f, a2 = 0.f;
        #pragma unroll
        for (int i = 0; i < 4; i++) {
            int cc = r * 4 + i;
            float4 w0 = W4[cc];
            float4 w1 = W4[32 + cc];
            float4 w2 = W4[64 + cc];
            a0 += xv[i].x * w0.x + xv[i].y * w0.y + xv[i].z * w0.z + xv[i].w * w0.w;
            a1 += xv[i].x * w1.x + xv[i].y * w1.y + xv[i].z * w1.z + xv[i].w * w1.w;
            a2 += xv[i].x * w2.x + xv[i].y * w2.y + xv[i].z * w2.z + xv[i].w * w2.w;
        }
        #pragma unroll
        for (int off = 4; off; off >>= 1) {
            a0 += __shfl_xor_sync(FULLM, a0, off);
            a1 += __shfl_xor_sync(FULLM, a1, off);
            a2 += __shfl_xor_sync(FULLM, a2, off);
        }
        if (r == 0) {
            const float* gr = gu + (size_t)row * 3;
            float g0 = -logf(-logf(gr[0] + EPSF) + EPSF);
            float g1 = -logf(-logf(gr[1] + EPSF) + EPSF);
            float g2 = -logf(-logf(gr[2] + EPSF) + EPSF);
            float s0 = a0 + bias[0] + g0;
            float s1 = a1 + bias[1] + g1;
            float s2 = a2 + bias[2] + g2;
            int tt = 0; float best = s0;
            if (s1 > best) { best = s1; tt = 1; }   // first-max tie-break
            if (s2 > best) { best = s2; tt = 2; }
            g_tt[row] = tt;
        }
    }
    __syncthreads();
    if (tid == 0) {
        __threadfence();                              // release g_tt
        sh_last = (atomicAdd(&g_cnt, 1u) == TTBLK - 1);
    }
    __syncthreads();
    if (!sh_last) return;

    // ---------------- last block: suffix-min scan, publish (lo,hi) ----------
    __threadfence();                                  // acquire all g_tt
    int lane = tid & 31, wid = tid >> 5;              // 16 warps
    for (int b = 0; b < BB; b++) {
        __syncthreads();                              // shared reuse guard
        int base = b * SS + tid * 4;                  // 4 elems/thread
        int t0 = g_tt[base + 0], t1 = g_tt[base + 1];
        int t2 = g_tt[base + 2], t3 = g_tt[base + 3];
        int j0 = tid * 4;
        int e0 = (t0 == 0) ? j0     : SS;
        int e1 = (t1 == 0) ? j0 + 1 : SS;
        int e2 = (t2 == 0) ? j0 + 2 : SS;
        int e3 = (t3 == 0) ? j0 + 3 : SS;
        int m  = min(min(e0, e1), min(e2, e3));

        int inc = m;                                  // warp suffix-min (inclusive)
        #pragma unroll
        for (int off = 1; off < 32; off <<= 1) {
            int v = __shfl_down_sync(FULLM, inc, off);
            if (lane + off < 32) inc = min(inc, v);
        }
        int excl = __shfl_down_sync(FULLM, inc, 1);
        if (lane == 31) excl = SS;

        if (lane == 0) sh_wmin[wid] = inc;
        __syncthreads();
        if (wid == 0) {
            int wm = (lane < 16) ? sh_wmin[lane] : SS;
            int winc = wm;
            #pragma unroll
            for (int off = 1; off < 16; off <<= 1)
                winc = min(winc, __shfl_down_sync(FULLM, winc, off));
            int wex = __shfl_down_sync(FULLM, winc, 1);  // lane15 gets lane16's SS
            if (lane < 16) sh_wsuf[lane] = wex;
        }
        __syncthreads();
        int after = min(excl, sh_wsuf[wid]);          // min over idx > 4t+3

        int run = after;
        int ng3 = run; run = min(run, e3);
        int ng2 = run; run = min(run, e2);
        int ng1 = run; run = min(run, e1);
        int ng0 = run;

        int2 lh;
        #define EMIT(ii, tt_, ng_)                                  \
            { int j = j0 + ii; lh.x = 0; lh.y = j;                  \
              if (tt_ == 1)      { lh.x = j; lh.y = j; }            \
              else if (tt_ == 2) { lh.y = min(j, ng_); }            \
              g_lohi[base + ii] = lh; }
        EMIT(0, t0, ng0); EMIT(1, t1, ng1);
        EMIT(2, t2, ng2); EMIT(3, t3, ng3);
        #undef EMIT
    }
    __syncthreads();
    if (tid == 0) g_cnt = 0;            // reset for next graph replay
}

// ---------------------------------------------------------------------------
// Kernel 2: one block per full output row. 512 threads x one float4 (8KB),
// branchless range test, streaming stores. R2/R3's proven 6.7 TB/s pattern.
// ---------------------------------------------------------------------------
__global__ void __launch_bounds__(512) k_write(float4* __restrict__ out) {
    int row = blockIdx.x;            // over B*H*S = 32768
    int s   = row & (SS - 1);
    int b   = row >> 14;             // / (H*S)
    int2 lh = g_lohi[b * SS + s];    // one broadcast 8B load per thread

    int j = threadIdx.x << 2;
    unsigned range = (unsigned)(lh.y - lh.x);
    float4 v;
    v.x = ((unsigned)(j     - lh.x) <= range) ? 1.f : 0.f;
    v.y = ((unsigned)(j + 1 - lh.x) <= range) ? 1.f : 0.f;
    v.z = ((unsigned)(j + 2 - lh.x) <= range) ? 1.f : 0.f;
    v.w = ((unsigned)(j + 3 - lh.x) <= range) ? 1.f : 0.f;
    __stcs(&out[(size_t)row * QROW + threadIdx.x], v);
}

extern "C" void kernel_launch(void* const* d_in, const int* in_sizes, int n_in,
                              void* d_out, int out_size) {
    const float* x    = (const float*)d_in[0];  // input_tensor (B,S,D)
    // d_in[1] = token_types (unused by reference)
    const float* gu   = (const float*)d_in[2];  // gumbel_u (B,S,3)
    const float* W    = (const float*)d_in[3];  // (3,D)
    const float* bias = (const float*)d_in[4];  // (3,)
    float4* out = (float4*)d_out;

    k_phase1<<<TTBLK, 512>>>(x, gu, W, bias);
    k_write<<<NROWS, 512>>>(out);
}

// round 13
// speedup vs baseline: 2.4859x; 1.0006x over previous
#include <cuda_runtime.h>

#define BB 2
#define SS 2048
#define DD 128
#define HH 8
#define EPSF 1e-10f
#define FULLM 0xffffffffu
#define TTBLK 64                 // phase-1 blocks (4096 rows, 8 thr/row, 512 thr/blk)
#define NROWS (BB * HH * SS)     // 32768 output rows
#define QROW  (SS / 4)           // 512 float4 per row

// Scratch (allocation-free rule: __device__ globals; zero-init at load)
__device__ int      g_tt[BB * SS];
__device__ int2     g_lohi[BB * SS];
__device__ unsigned g_cnt = 0;

// ---------------------------------------------------------------------------
// Kernel 1 (grid 64): tt argmax + suffix-min scan -> g_lohi.
// Exact logic validated since R7 (rel_err = 0).
// ---------------------------------------------------------------------------
__global__ void __launch_bounds__(512) k_phase1(const float* __restrict__ x,
                                                const float* __restrict__ gu,
                                                const float* __restrict__ W,
                                                const float* __restrict__ bias) {
    const int tid = threadIdx.x;
    const int bid = blockIdx.x;

    __shared__ int sh_last;
    __shared__ int sh_wmin[16];
    __shared__ int sh_wsuf[16];

    {
        int gid = bid * 512 + tid;
        int row = gid >> 3;              // 0..4095 = b*S + s
        int r   = gid & 7;

        const float4* xr = reinterpret_cast<const float4*>(x + (size_t)row * DD);
        const float4* W4 = reinterpret_cast<const float4*>(W);

        float4 xv[4];
        #pragma unroll
        for (int i = 0; i < 4; i++) xv[i] = xr[r * 4 + i];

        float a0 = 0.f, a1 = 0.f, a2 = 0.f;
        #pragma unroll
        for (int i = 0; i < 4; i++) {
            int cc = r * 4 + i;
            float4 w0 = W4[cc];
            float4 w1 = W4[32 + cc];
            float4 w2 = W4[64 + cc];
            a0 += xv[i].x * w0.x + xv[i].y * w0.y + xv[i].z * w0.z + xv[i].w * w0.w;
            a1 += xv[i].x * w1.x + xv[i].y * w1.y + xv[i].z * w1.z + xv[i].w * w1.w;
            a2 += xv[i].x * w2.x + xv[i].y * w2.y + xv[i].z * w2.z + xv[i].w * w2.w;
        }
        #pragma unroll
        for (int off = 4; off; off >>= 1) {
            a0 += __shfl_xor_sync(FULLM, a0, off);
            a1 += __shfl_xor_sync(FULLM, a1, off);
            a2 += __shfl_xor_sync(FULLM, a2, off);
        }
        if (r == 0) {
            const float* gr = gu + (size_t)row * 3;
            float g0 = -logf(-logf(gr[0] + EPSF) + EPSF);
            float g1 = -logf(-logf(gr[1] + EPSF) + EPSF);
            float g2 = -logf(-logf(gr[2] + EPSF) + EPSF);
            float s0 = a0 + bias[0] + g0;
            float s1 = a1 + bias[1] + g1;
            float s2 = a2 + bias[2] + g2;
            int tt = 0; float best = s0;
            if (s1 > best) { best = s1; tt = 1; }   // first-max tie-break
            if (s2 > best) { best = s2; tt = 2; }
            g_tt[row] = tt;
        }
    }
    __syncthreads();
    if (tid == 0) {
        __threadfence();                              // release g_tt
        sh_last = (atomicAdd(&g_cnt, 1u) == TTBLK - 1);
    }
    __syncthreads();
    if (!sh_last) return;

    // ---------------- last block: suffix-min scan, publish (lo,hi) ----------
    __threadfence();                                  // acquire all g_tt
    int lane = tid & 31, wid = tid >> 5;              // 16 warps
    for (int b = 0; b < BB; b++) {
        __syncthreads();                              // shared reuse guard
        int base = b * SS + tid * 4;                  // 4 elems/thread
        int t0 = g_tt[base + 0], t1 = g_tt[base + 1];
        int t2 = g_tt[base + 2], t3 = g_tt[base + 3];
        int j0 = tid * 4;
        int e0 = (t0 == 0) ? j0     : SS;
        int e1 = (t1 == 0) ? j0 + 1 : SS;
        int e2 = (t2 == 0) ? j0 + 2 : SS;
        int e3 = (t3 == 0) ? j0 + 3 : SS;
        int m  = min(min(e0, e1), min(e2, e3));

        int inc = m;                                  // warp suffix-min (inclusive)
        #pragma unroll
        for (int off = 1; off < 32; off <<= 1) {
            int v = __shfl_down_sync(FULLM, inc, off);
            if (lane + off < 32) inc = min(inc, v);
        }
        int excl = __shfl_down_sync(FULLM, inc, 1);
        if (lane == 31) excl = SS;

        if (lane == 0) sh_wmin[wid] = inc;
        __syncthreads();
        if (wid == 0) {
            int wm = (lane < 16) ? sh_wmin[lane] : SS;
            int winc = wm;
            #pragma unroll
            for (int off = 1; off < 16; off <<= 1)
                winc = min(winc, __shfl_down_sync(FULLM, winc, off));
            int wex = __shfl_down_sync(FULLM, winc, 1);  // lane15 gets lane16's SS
            if (lane < 16) sh_wsuf[lane] = wex;
        }
        __syncthreads();
        int after = min(excl, sh_wsuf[wid]);          // min over idx > 4t+3

        int run = after;
        int ng3 = run; run = min(run, e3);
        int ng2 = run; run = min(run, e2);
        int ng1 = run; run = min(run, e1);
        int ng0 = run;

        int2 lh;
        #define EMIT(ii, tt_, ng_)                                  \
            { int j = j0 + ii; lh.x = 0; lh.y = j;                  \
              if (tt_ == 1)      { lh.x = j; lh.y = j; }            \
              else if (tt_ == 2) { lh.y = min(j, ng_); }            \
              g_lohi[base + ii] = lh; }
        EMIT(0, t0, ng0); EMIT(1, t1, ng1);
        EMIT(2, t2, ng2); EMIT(3, t3, ng3);
        #undef EMIT
    }
    __syncthreads();
    if (tid == 0) g_cnt = 0;            // reset for next graph replay
}

// ---------------------------------------------------------------------------
// Kernel 2: one block per full output row. 256 threads x two float4 stores
// (ILP=2), plain stores, simple compares — the R2/R3 proven fast writer.
// ---------------------------------------------------------------------------
__global__ void __launch_bounds__(256) k_write(float4* __restrict__ out) {
    int row = blockIdx.x;            // over B*H*S = 32768
    int s   = row & (SS - 1);
    int b   = row >> 14;             // / (H*S)
    int2 lh = g_lohi[b * SS + s];    // one broadcast 8B load per thread
    int lo = lh.x, hi = lh.y;

    float4* orow = out + (size_t)row * QROW;
    int tid = threadIdx.x;
    #pragma unroll
    for (int it = 0; it < 2; it++) {
        int q = it * 256 + tid;
        int j = q << 2;
        float4 v;
        v.x = (j     >= lo && j     <= hi) ? 1.0f : 0.0f;
        v.y = (j + 1 >= lo && j + 1 <= hi) ? 1.0f : 0.0f;
        v.z = (j + 2 >= lo && j + 2 <= hi) ? 1.0f : 0.0f;
        v.w = (j + 3 >= lo && j + 3 <= hi) ? 1.0f : 0.0f;
        orow[q] = v;
    }
}

extern "C" void kernel_launch(void* const* d_in, const int* in_sizes, int n_in,
                              void* d_out, int out_size) {
    const float* x    = (const float*)d_in[0];  // input_tensor (B,S,D)
    // d_in[1] = token_types (unused by reference)
    const float* gu   = (const float*)d_in[2];  // gumbel_u (B,S,3)
    const float* W    = (const float*)d_in[3];  // (3,D)
    const float* bias = (const float*)d_in[4];  // (3,)
    float4* out = (float4*)d_out;

    k_phase1<<<TTBLK, 512>>>(x, gu, W, bias);
    k_write<<<NROWS, 256>>>(out);
}

// round 14
// speedup vs baseline: 2.5862x; 1.0403x over previous
#include <cuda_runtime.h>

#define BB 2
#define SS 2048
#define DD 128
#define HH 8
#define EPSF 1e-10f
#define FULLM 0xffffffffu
#define P1BLK 512                // phase-1 blocks: 4096 rows, warp per row, 256 thr
#define NROWS (BB * HH * SS)     // 32768 output rows
#define QROW  (SS / 4)           // 512 float4 per row

// Scratch (allocation-free rule: __device__ globals; zero-init at load)
__device__ int      g_tt[BB * SS];
__device__ int2     g_lohi[BB * SS];
__device__ unsigned g_cnt = 0;

// ---------------------------------------------------------------------------
// Kernel 1 (grid 512 x 256): one warp per (b,s) row — R2's measured-5.34us
// argmax layout — then the last-arriving block runs the suffix-min scan
// (256 threads x 8 elements) and publishes g_lohi.
// ---------------------------------------------------------------------------
__global__ void __launch_bounds__(256) k_phase1(const float* __restrict__ x,
                                                const float* __restrict__ gu,
                                                const float* __restrict__ W,
                                                const float* __restrict__ bias) {
    const int tid = threadIdx.x;
    const int bid = blockIdx.x;

    __shared__ int sh_last;
    __shared__ int sh_wmin[8];
    __shared__ int sh_wsuf[8];

    // ---------------- argmax: warp per row ----------------
    {
        int gwarp = (bid * 256 + tid) >> 5;   // 0..4095 = b*S + s
        int lane  = tid & 31;

        const float4* xr = reinterpret_cast<const float4*>(x + (size_t)gwarp * DD);
        float4 xv = xr[lane];                 // 32 lanes * 4 = 128, coalesced

        const float4* W4 = reinterpret_cast<const float4*>(W);
        float a0, a1, a2;
        {
            float4 w0 = W4[lane];
            float4 w1 = W4[32 + lane];
            float4 w2 = W4[64 + lane];
            a0 = xv.x * w0.x + xv.y * w0.y + xv.z * w0.z + xv.w * w0.w;
            a1 = xv.x * w1.x + xv.y * w1.y + xv.z * w1.z + xv.w * w1.w;
            a2 = xv.x * w2.x + xv.y * w2.y + xv.z * w2.z + xv.w * w2.w;
        }
        #pragma unroll
        for (int off = 16; off; off >>= 1) {
            a0 += __shfl_xor_sync(FULLM, a0, off);
            a1 += __shfl_xor_sync(FULLM, a1, off);
            a2 += __shfl_xor_sync(FULLM, a2, off);
        }
        if (lane == 0) {
            const float* gr = gu + (size_t)gwarp * 3;
            float g0 = -logf(-logf(gr[0] + EPSF) + EPSF);
            float g1 = -logf(-logf(gr[1] + EPSF) + EPSF);
            float g2 = -logf(-logf(gr[2] + EPSF) + EPSF);
            float s0 = a0 + bias[0] + g0;
            float s1 = a1 + bias[1] + g1;
            float s2 = a2 + bias[2] + g2;
            int tt = 0; float best = s0;
            if (s1 > best) { best = s1; tt = 1; }   // first-max tie-break
            if (s2 > best) { best = s2; tt = 2; }
            g_tt[gwarp] = tt;
        }
    }
    __syncthreads();
    if (tid == 0) {
        __threadfence();                              // release g_tt
        sh_last = (atomicAdd(&g_cnt, 1u) == P1BLK - 1);
    }
    __syncthreads();
    if (!sh_last) return;

    // ---------------- last block: suffix-min scan, publish (lo,hi) ----------
    __threadfence();                                  // acquire all g_tt
    int lane = tid & 31, wid = tid >> 5;              // 8 warps x 32 lanes
    for (int b = 0; b < BB; b++) {
        __syncthreads();                              // shared reuse guard
        int base = b * SS + tid * 8;                  // 8 elems per thread
        int tts[8], e[8];
        int j0 = tid * 8;
        int m = SS;
        #pragma unroll
        for (int i = 0; i < 8; i++) {
            tts[i] = g_tt[base + i];
            e[i]   = (tts[i] == 0) ? j0 + i : SS;
            m      = min(m, e[i]);
        }

        int inc = m;                                  // warp suffix-min (inclusive)
        #pragma unroll
        for (int off = 1; off < 32; off <<= 1) {
            int v = __shfl_down_sync(FULLM, inc, off);
            if (lane + off < 32) inc = min(inc, v);
        }
        int excl = __shfl_down_sync(FULLM, inc, 1);
        if (lane == 31) excl = SS;

        if (lane == 0) sh_wmin[wid] = inc;
        __syncthreads();
        if (wid == 0) {
            int wm = (lane < 8) ? sh_wmin[lane] : SS;
            int winc = wm;
            #pragma unroll
            for (int off = 1; off < 8; off <<= 1) {
                int v = __shfl_down_sync(FULLM, winc, off);
                if (lane + off < 8) winc = min(winc, v);
            }
            int wex = __shfl_down_sync(FULLM, winc, 1);  // lane7 gets lane8's SS
            if (lane < 8) sh_wsuf[lane] = wex;
        }
        __syncthreads();
        int after = min(excl, sh_wsuf[wid]);          // min over idx > j0+7

        int run = after;                              // right-to-left next_global
        int ng[8];
        #pragma unroll
        for (int i = 7; i >= 0; i--) {
            ng[i] = run;
            run   = min(run, e[i]);
        }

        #pragma unroll
        for (int i = 0; i < 8; i++) {
            int j = j0 + i;
            int2 lh; lh.x = 0; lh.y = j;
            if (tts[i] == 1)      { lh.x = j; lh.y = j; }
            else if (tts[i] == 2) { lh.y = min(j, ng[i]); }
            g_lohi[base + i] = lh;
        }
    }
    __syncthreads();
    if (tid == 0) g_cnt = 0;            // reset for next graph replay
}

// ---------------------------------------------------------------------------
// Kernel 2: one block per full output row. 256 threads x two float4 stores
// (ILP=2), plain stores, simple compares — measured 39.4us (6.8 TB/s).
// ---------------------------------------------------------------------------
__global__ void __launch_bounds__(256) k_write(float4* __restrict__ out) {
    int row = blockIdx.x;            // over B*H*S = 32768
    int s   = row & (SS - 1);
    int b   = row >> 14;             // / (H*S)
    int2 lh = g_lohi[b * SS + s];    // one broadcast 8B load per thread
    int lo = lh.x, hi = lh.y;

    float4* orow = out + (size_t)row * QROW;
    int tid = threadIdx.x;
    #pragma unroll
    for (int it = 0; it < 2; it++) {
        int q = it * 256 + tid;
        int j = q << 2;
        float4 v;
        v.x = (j     >= lo && j     <= hi) ? 1.0f : 0.0f;
        v.y = (j + 1 >= lo && j + 1 <= hi) ? 1.0f : 0.0f;
        v.z = (j + 2 >= lo && j + 2 <= hi) ? 1.0f : 0.0f;
        v.w = (j + 3 >= lo && j + 3 <= hi) ? 1.0f : 0.0f;
        orow[q] = v;
    }
}

extern "C" void kernel_launch(void* const* d_in, const int* in_sizes, int n_in,
                              void* d_out, int out_size) {
    const float* x    = (const float*)d_in[0];  // input_tensor (B,S,D)
    // d_in[1] = token_types (unused by reference)
    const float* gu   = (const float*)d_in[2];  // gumbel_u (B,S,3)
    const float* W    = (const float*)d_in[3];  // (3,D)
    const float* bias = (const float*)d_in[4];  // (3,)
    float4* out = (float4*)d_out;

    k_phase1<<<P1BLK, 256>>>(x, gu, W, bias);
    k_write<<<NROWS, 256>>>(out);
}

// round 15
// speedup vs baseline: 2.6986x; 1.0434x over previous
#include <cuda_runtime.h>

#define BB 2
#define SS 2048
#define DD 128
#define HH 8
#define EPSF 1e-10f
#define FULLM 0xffffffffu
#define P1BLK 512                // phase-1 blocks: 4096 rows, warp per row, 256 thr
#define BPB   (P1BLK / BB)       // 256 phase-1 blocks per batch
#define NROWS (BB * HH * SS)     // 32768 output rows
#define QROW  (SS / 4)           // 512 float4 per row

// Scratch (allocation-free rule: __device__ globals; zero-init at load)
__device__ int      g_tt[BB * SS];
__device__ int2     g_lohi[BB * SS];
__device__ unsigned g_cnt2[BB] = {0, 0};

// ---------------------------------------------------------------------------
// Kernel 1 (grid 512 x 256): one warp per (b,s) row (R2's 5.34us layout).
// Blocks [256b, 256b+256) own batch b; the last arrival PER BATCH scans that
// batch (256 thr x 8 elems) and publishes g_lohi. Each block triggers PDL
// completion right after its g_tt contribution so k_write can ramp early.
// ---------------------------------------------------------------------------
__global__ void __launch_bounds__(256) k_phase1(const float* __restrict__ x,
                                                const float* __restrict__ gu,
                                                const float* __restrict__ W,
                                                const float* __restrict__ bias) {
    const int tid = threadIdx.x;
    const int bid = blockIdx.x;

    __shared__ int sh_last;
    __shared__ int sh_wmin[8];
    __shared__ int sh_wsuf[8];

    // ---------------- argmax: warp per row ----------------
    {
        int gwarp = (bid * 256 + tid) >> 5;   // 0..4095 = b*S + s
        int lane  = tid & 31;

        const float4* xr = reinterpret_cast<const float4*>(x + (size_t)gwarp * DD);
        float4 xv = xr[lane];                 // 32 lanes * 4 = 128, coalesced

        const float4* W4 = reinterpret_cast<const float4*>(W);
        float a0, a1, a2;
        {
            float4 w0 = W4[lane];
            float4 w1 = W4[32 + lane];
            float4 w2 = W4[64 + lane];
            a0 = xv.x * w0.x + xv.y * w0.y + xv.z * w0.z + xv.w * w0.w;
            a1 = xv.x * w1.x + xv.y * w1.y + xv.z * w1.z + xv.w * w1.w;
            a2 = xv.x * w2.x + xv.y * w2.y + xv.z * w2.z + xv.w * w2.w;
        }
        #pragma unroll
        for (int off = 16; off; off >>= 1) {
            a0 += __shfl_xor_sync(FULLM, a0, off);
            a1 += __shfl_xor_sync(FULLM, a1, off);
            a2 += __shfl_xor_sync(FULLM, a2, off);
        }
        if (lane == 0) {
            const float* gr = gu + (size_t)gwarp * 3;
            float g0 = -logf(-logf(gr[0] + EPSF) + EPSF);
            float g1 = -logf(-logf(gr[1] + EPSF) + EPSF);
            float g2 = -logf(-logf(gr[2] + EPSF) + EPSF);
            float s0 = a0 + bias[0] + g0;
            float s1 = a1 + bias[1] + g1;
            float s2 = a2 + bias[2] + g2;
            int tt = 0; float best = s0;
            if (s1 > best) { best = s1; tt = 1; }   // first-max tie-break
            if (s2 > best) { best = s2; tt = 2; }
            g_tt[gwarp] = tt;
        }
    }
    __syncthreads();

    const int b = bid / BPB;                          // this block's batch
    if (tid == 0) {
        __threadfence();                              // release g_tt
        sh_last = (atomicAdd(&g_cnt2[b], 1u) == BPB - 1);
#if __CUDA_ARCH__ >= 900
        cudaTriggerProgrammaticLaunchCompletion();    // let k_write ramp
#endif
    }
    __syncthreads();
    if (!sh_last) return;

    // ------- last block of batch b: suffix-min scan, publish (lo,hi) -------
    __threadfence();                                  // acquire batch's g_tt
    int lane = tid & 31, wid = tid >> 5;              // 8 warps x 32 lanes
    {
        int base = b * SS + tid * 8;                  // 8 elems per thread
        int tts[8], e[8];
        int j0 = tid * 8;
        int m = SS;
        #pragma unroll
        for (int i = 0; i < 8; i++) {
            tts[i] = g_tt[base + i];
            e[i]   = (tts[i] == 0) ? j0 + i : SS;
            m      = min(m, e[i]);
        }

        int inc = m;                                  // warp suffix-min (inclusive)
        #pragma unroll
        for (int off = 1; off < 32; off <<= 1) {
            int v = __shfl_down_sync(FULLM, inc, off);
            if (lane + off < 32) inc = min(inc, v);
        }
        int excl = __shfl_down_sync(FULLM, inc, 1);
        if (lane == 31) excl = SS;

        if (lane == 0) sh_wmin[wid] = inc;
        __syncthreads();
        if (wid == 0) {
            int wm = (lane < 8) ? sh_wmin[lane] : SS;
            int winc = wm;
            #pragma unroll
            for (int off = 1; off < 8; off <<= 1) {
                int v = __shfl_down_sync(FULLM, winc, off);
                if (lane + off < 8) winc = min(winc, v);
            }
            int wex = __shfl_down_sync(FULLM, winc, 1);  // lane7 gets lane8's SS
            if (lane < 8) sh_wsuf[lane] = wex;
        }
        __syncthreads();
        int after = min(excl, sh_wsuf[wid]);          // min over idx > j0+7

        int run = after;                              // right-to-left next_global
        int ng[8];
        #pragma unroll
        for (int i = 7; i >= 0; i--) {
            ng[i] = run;
            run   = min(run, e[i]);
        }

        #pragma unroll
        for (int i = 0; i < 8; i++) {
            int j = j0 + i;
            int2 lh; lh.x = 0; lh.y = j;
            if (tts[i] == 1)      { lh.x = j; lh.y = j; }
            else if (tts[i] == 2) { lh.y = min(j, ng[i]); }
            g_lohi[base + i] = lh;
        }
    }
    __syncthreads();
    if (tid == 0) g_cnt2[b] = 0;        // reset for next graph replay
}

// ---------------------------------------------------------------------------
// Kernel 2: one block per full output row. 256 threads x two float4 stores,
// plain stores, simple compares — measured 39.4-39.7us (6.8 TB/s).
// Launched with PDL: ramps during phase-1 tail, syncs before reading g_lohi.
// ---------------------------------------------------------------------------
__global__ void __launch_bounds__(256) k_write(float4* __restrict__ out) {
    int row = blockIdx.x;            // over B*H*S = 32768
    int s   = row & (SS - 1);
    int b   = row >> 14;             // / (H*S)
    float4* orow = out + (size_t)row * QROW;
    int tid = threadIdx.x;

#if __CUDA_ARCH__ >= 900
    cudaGridDependencySynchronize(); // wait: all phase-1 memory visible
#endif

    int2 lh = g_lohi[b * SS + s];    // one broadcast 8B load per thread
    int lo = lh.x, hi = lh.y;
    #pragma unroll
    for (int it = 0; it < 2; it++) {
        int q = it * 256 + tid;
        int j = q << 2;
        float4 v;
        v.x = (j     >= lo && j     <= hi) ? 1.0f : 0.0f;
        v.y = (j + 1 >= lo && j + 1 <= hi) ? 1.0f : 0.0f;
        v.z = (j + 2 >= lo && j + 2 <= hi) ? 1.0f : 0.0f;
        v.w = (j + 3 >= lo && j + 3 <= hi) ? 1.0f : 0.0f;
        orow[q] = v;
    }
}

extern "C" void kernel_launch(void* const* d_in, const int* in_sizes, int n_in,
                              void* d_out, int out_size) {
    const float* x    = (const float*)d_in[0];  // input_tensor (B,S,D)
    // d_in[1] = token_types (unused by reference)
    const float* gu   = (const float*)d_in[2];  // gumbel_u (B,S,3)
    const float* W    = (const float*)d_in[3];  // (3,D)
    const float* bias = (const float*)d_in[4];  // (3,)
    float4* out = (float4*)d_out;

    k_phase1<<<P1BLK, 256>>>(x, gu, W, bias);

    // k_write with programmatic dependent launch (overlaps phase-1 tail).
    cudaLaunchConfig_t cfg = {};
    cfg.gridDim  = dim3(NROWS, 1, 1);
    cfg.blockDim = dim3(256, 1, 1);
    cfg.dynamicSmemBytes = 0;
    cfg.stream = 0;
    cudaLaunchAttribute attr[1];
    attr[0].id = cudaLaunchAttributeProgrammaticStreamSerialization;
    attr[0].val.programmaticStreamSerializationAllowed = 1;
    cfg.attrs = attr;
    cfg.numAttrs = 1;
    cudaLaunchKernelEx(&cfg, k_write, out);
}

// round 16
// speedup vs baseline: 2.7004x; 1.0007x over previous
#include <cuda_runtime.h>

#define BB 2
#define SS 2048
#define DD 128
#define HH 8
#define EPSF 1e-10f
#define FULLM 0xffffffffu
#define P1BLK 512                // phase-1 blocks: 4096 rows, warp per row, 256 thr
#define BPB   (P1BLK / BB)       // 256 phase-1 blocks per batch
#define NROWS (BB * HH * SS)     // 32768 output rows
#define QROW  (SS / 4)           // 512 float4 per row

// Scratch (allocation-free rule: __device__ globals; zero-init at load)
__device__ int      g_tt[BB * SS];
__device__ int2     g_lohi[BB * SS];
__device__ unsigned g_cnt2[BB] = {0, 0};

// ---------------------------------------------------------------------------
// Kernel 1 (grid 512 x 256): one warp per (b,s) row. Last arrival PER BATCH
// scans that batch and publishes g_lohi. PDL-trigger after g_tt contribution.
// (Unchanged from R15 — validated, rel_err = 0.)
// ---------------------------------------------------------------------------
__global__ void __launch_bounds__(256) k_phase1(const float* __restrict__ x,
                                                const float* __restrict__ gu,
                                                const float* __restrict__ W,
                                                const float* __restrict__ bias) {
    const int tid = threadIdx.x;
    const int bid = blockIdx.x;

    __shared__ int sh_last;
    __shared__ int sh_wmin[8];
    __shared__ int sh_wsuf[8];

    // ---------------- argmax: warp per row ----------------
    {
        int gwarp = (bid * 256 + tid) >> 5;   // 0..4095 = b*S + s
        int lane  = tid & 31;

        const float4* xr = reinterpret_cast<const float4*>(x + (size_t)gwarp * DD);
        float4 xv = xr[lane];                 // 32 lanes * 4 = 128, coalesced

        const float4* W4 = reinterpret_cast<const float4*>(W);
        float a0, a1, a2;
        {
            float4 w0 = W4[lane];
            float4 w1 = W4[32 + lane];
            float4 w2 = W4[64 + lane];
            a0 = xv.x * w0.x + xv.y * w0.y + xv.z * w0.z + xv.w * w0.w;
            a1 = xv.x * w1.x + xv.y * w1.y + xv.z * w1.z + xv.w * w1.w;
            a2 = xv.x * w2.x + xv.y * w2.y + xv.z * w2.z + xv.w * w2.w;
        }
        #pragma unroll
        for (int off = 16; off; off >>= 1) {
            a0 += __shfl_xor_sync(FULLM, a0, off);
            a1 += __shfl_xor_sync(FULLM, a1, off);
            a2 += __shfl_xor_sync(FULLM, a2, off);
        }
        if (lane == 0) {
            const float* gr = gu + (size_t)gwarp * 3;
            float g0 = -logf(-logf(gr[0] + EPSF) + EPSF);
            float g1 = -logf(-logf(gr[1] + EPSF) + EPSF);
            float g2 = -logf(-logf(gr[2] + EPSF) + EPSF);
            float s0 = a0 + bias[0] + g0;
            float s1 = a1 + bias[1] + g1;
            float s2 = a2 + bias[2] + g2;
            int tt = 0; float best = s0;
            if (s1 > best) { best = s1; tt = 1; }   // first-max tie-break
            if (s2 > best) { best = s2; tt = 2; }
            g_tt[gwarp] = tt;
        }
    }
    __syncthreads();

    const int b = bid / BPB;                          // this block's batch
    if (tid == 0) {
        __threadfence();                              // release g_tt
        sh_last = (atomicAdd(&g_cnt2[b], 1u) == BPB - 1);
#if __CUDA_ARCH__ >= 900
        cudaTriggerProgrammaticLaunchCompletion();    // let k_write ramp
#endif
    }
    __syncthreads();
    if (!sh_last) return;

    // ------- last block of batch b: suffix-min scan, publish (lo,hi) -------
    __threadfence();                                  // acquire batch's g_tt
    int lane = tid & 31, wid = tid >> 5;              // 8 warps x 32 lanes
    {
        int base = b * SS + tid * 8;                  // 8 elems per thread
        int tts[8], e[8];
        int j0 = tid * 8;
        int m = SS;
        #pragma unroll
        for (int i = 0; i < 8; i++) {
            tts[i] = g_tt[base + i];
            e[i]   = (tts[i] == 0) ? j0 + i : SS;
            m      = min(m, e[i]);
        }

        int inc = m;                                  // warp suffix-min (inclusive)
        #pragma unroll
        for (int off = 1; off < 32; off <<= 1) {
            int v = __shfl_down_sync(FULLM, inc, off);
            if (lane + off < 32) inc = min(inc, v);
        }
        int excl = __shfl_down_sync(FULLM, inc, 1);
        if (lane == 31) excl = SS;

        if (lane == 0) sh_wmin[wid] = inc;
        __syncthreads();
        if (wid == 0) {
            int wm = (lane < 8) ? sh_wmin[lane] : SS;
            int winc = wm;
            #pragma unroll
            for (int off = 1; off < 8; off <<= 1) {
                int v = __shfl_down_sync(FULLM, winc, off);
                if (lane + off < 8) winc = min(winc, v);
            }
            int wex = __shfl_down_sync(FULLM, winc, 1);  // lane7 gets lane8's SS
            if (lane < 8) sh_wsuf[lane] = wex;
        }
        __syncthreads();
        int after = min(excl, sh_wsuf[wid]);          // min over idx > j0+7

        int run = after;                              // right-to-left next_global
        int ng[8];
        #pragma unroll
        for (int i = 7; i >= 0; i--) {
            ng[i] = run;
            run   = min(run, e[i]);
        }

        #pragma unroll
        for (int i = 0; i < 8; i++) {
            int j = j0 + i;
            int2 lh; lh.x = 0; lh.y = j;
            if (tts[i] == 1)      { lh.x = j; lh.y = j; }
            else if (tts[i] == 2) { lh.y = min(j, ng[i]); }
            g_lohi[base + i] = lh;
        }
    }
    __syncthreads();
    if (tid == 0) g_cnt2[b] = 0;        // reset for next graph replay
}

// ---------------------------------------------------------------------------
// Kernel 2: TWO adjacent rows per block (contiguous 16KB span), 256 threads,
// 4 independent float4 stores per thread. PDL sync before reading g_lohi.
// ---------------------------------------------------------------------------
__global__ void __launch_bounds__(256) k_write(float4* __restrict__ out) {
    int row0 = blockIdx.x << 1;          // rows row0, row0+1 (same b,h)
    int s0   = row0 & (SS - 1);
    int b    = row0 >> 14;               // / (H*S)
    int tid  = threadIdx.x;

#if __CUDA_ARCH__ >= 900
    cudaGridDependencySynchronize();     // all phase-1 memory visible
#endif

    int2 lhA = g_lohi[b * SS + s0];      // two independent 8B loads (MLP=2)
    int2 lhB = g_lohi[b * SS + s0 + 1];

    float4* orow = out + (size_t)row0 * QROW;   // 1024 contiguous quads
    #pragma unroll
    for (int it = 0; it < 2; it++) {
        int q = it * 256 + tid;
        int j = q << 2;
        float4 va, vb;
        va.x = (j     >= lhA.x && j     <= lhA.y) ? 1.0f : 0.0f;
        va.y = (j + 1 >= lhA.x && j + 1 <= lhA.y) ? 1.0f : 0.0f;
        va.z = (j + 2 >= lhA.x && j + 2 <= lhA.y) ? 1.0f : 0.0f;
        va.w = (j + 3 >= lhA.x && j + 3 <= lhA.y) ? 1.0f : 0.0f;
        vb.x = (j     >= lhB.x && j     <= lhB.y) ? 1.0f : 0.0f;
        vb.y = (j + 1 >= lhB.x && j + 1 <= lhB.y) ? 1.0f : 0.0f;
        vb.z = (j + 2 >= lhB.x && j + 2 <= lhB.y) ? 1.0f : 0.0f;
        vb.w = (j + 3 >= lhB.x && j + 3 <= lhB.y) ? 1.0f : 0.0f;
        orow[q]        = va;
        orow[QROW + q] = vb;
    }
}

extern "C" void kernel_launch(void* const* d_in, const int* in_sizes, int n_in,
                              void* d_out, int out_size) {
    const float* x    = (const float*)d_in[0];  // input_tensor (B,S,D)
    // d_in[1] = token_types (unused by reference)
    const float* gu   = (const float*)d_in[2];  // gumbel_u (B,S,3)
    const float* W    = (const float*)d_in[3];  // (3,D)
    const float* bias = (const float*)d_in[4];  // (3,)
    float4* out = (float4*)d_out;

    k_phase1<<<P1BLK, 256>>>(x, gu, W, bias);

    // k_write with programmatic dependent launch (overlaps phase-1 tail).
    cudaLaunchConfig_t cfg = {};
    cfg.gridDim  = dim3(NROWS / 2, 1, 1);
    cfg.blockDim = dim3(256, 1, 1);
    cfg.dynamicSmemBytes = 0;
    cfg.stream = 0;
    cudaLaunchAttribute attr[1];
    attr[0].id = cudaLaunchAttributeProgrammaticStreamSerialization;
    attr[0].val.programmaticStreamSerializationAllowed = 1;
    cfg.attrs = attr;
    cfg.numAttrs = 1;
    cudaLaunchKernelEx(&cfg, k_write, out);
}